// round 3
// baseline (speedup 1.0000x reference)
#include <cuda_runtime.h>
#include <cstdint>

#define N_NODES 100000
#define N_EDGES 1600000
#define D 64
#define D4 16
#define CAP 64                 // max degree capacity per node (mean deg = 16)
#define BN_EPS 1e-5f

// ---------------- scratch ----------------
__device__ float g_y [N_NODES * D];        // MLP output (pre-BN)
__device__ int   g_deg[N_NODES];
__device__ int   g_srt[(size_t)N_NODES * CAP];   // src ids bucketed by dst
__device__ float g_sum[D];
__device__ float g_sq [D];

// ---------------- k0: zero degree array ----------------
__global__ void k_zero_deg()
{
    int i = blockIdx.x * blockDim.x + threadIdx.x;
    if (i < N_NODES) g_deg[i] = 0;
}

// ---------------- k1: bucket edges by dst ----------------
__global__ void k_bucket(const int* __restrict__ src, const int* __restrict__ dst)
{
    int e = blockIdx.x * blockDim.x + threadIdx.x;
    if (e >= N_EDGES) return;
    int d = dst[e];
    int p = atomicAdd(&g_deg[d], 1);
    if (p < CAP) g_srt[(size_t)d * CAP + p] = src[e];
}

// ---------------- k2: zero BN sums (tiny) ----------------
__global__ void k_zero_sums()
{
    int i = threadIdx.x;
    if (i < D) { g_sum[i] = 0.f; g_sq[i] = 0.f; }
}

// ---------------- k3: fused gather + MLP + BN-stats ----------------
// block = 256 threads handles 64 nodes. thread: r = tid/4 (row), c0 = (tid%4)*16
__global__ __launch_bounds__(256) void k_fused(const float4* __restrict__ feat4,
                                               const float* __restrict__ eps,
                                               const float* __restrict__ W1,
                                               const float* __restrict__ b1,
                                               const float* __restrict__ W2,
                                               const float* __restrict__ b2)
{
    __shared__ float hs[64][68];       // 68 stride: 16B-aligned rows, conflict-free cols
    __shared__ float ws[4096];
    __shared__ float bs1[64], bs2[64];
    __shared__ float ssum[64], ssq[64];

    int tid  = threadIdx.x;
    int base = blockIdx.x * 64;
    int r    = tid >> 2;               // 0..63
    int q    = tid & 3;
    int c0   = q * 16;
    int node = base + r;

    // start W1 load (independent of gather)
    for (int i = tid; i < 4096; i += 256) ws[i] = W1[i];
    if (tid < 64) {
        bs1[tid] = b1[tid];
        bs2[tid] = b2[tid];
        ssum[tid] = 0.f;
        ssq [tid] = 0.f;
    }

    // ---- gather: acc = (1+eps)*x[node] + sum_{s in N(node)} x[s], lanes c0..c0+15
    float4 a0, a1, a2, a3;
    if (node < N_NODES) {
        float se = 1.0f + *eps;
        const float4* fp = feat4 + (size_t)node * D4 + q * 4;
        a0 = fp[0]; a1 = fp[1]; a2 = fp[2]; a3 = fp[3];
        a0.x*=se; a0.y*=se; a0.z*=se; a0.w*=se;
        a1.x*=se; a1.y*=se; a1.z*=se; a1.w*=se;
        a2.x*=se; a2.y*=se; a2.z*=se; a2.w*=se;
        a3.x*=se; a3.y*=se; a3.z*=se; a3.w*=se;

        int dg = g_deg[node];
        if (dg > CAP) dg = CAP;
        const int* lst = g_srt + (size_t)node * CAP;
        int j = 0;
        for (; j + 2 <= dg; j += 2) {
            int s0 = lst[j], s1 = lst[j + 1];
            const float4* p0 = feat4 + (size_t)s0 * D4 + q * 4;
            const float4* p1 = feat4 + (size_t)s1 * D4 + q * 4;
            float4 v00=p0[0], v01=p0[1], v02=p0[2], v03=p0[3];
            float4 v10=p1[0], v11=p1[1], v12=p1[2], v13=p1[3];
            a0.x+=v00.x+v10.x; a0.y+=v00.y+v10.y; a0.z+=v00.z+v10.z; a0.w+=v00.w+v10.w;
            a1.x+=v01.x+v11.x; a1.y+=v01.y+v11.y; a1.z+=v01.z+v11.z; a1.w+=v01.w+v11.w;
            a2.x+=v02.x+v12.x; a2.y+=v02.y+v12.y; a2.z+=v02.z+v12.z; a2.w+=v02.w+v12.w;
            a3.x+=v03.x+v13.x; a3.y+=v03.y+v13.y; a3.z+=v03.z+v13.z; a3.w+=v03.w+v13.w;
        }
        if (j < dg) {
            int s0 = lst[j];
            const float4* p0 = feat4 + (size_t)s0 * D4 + q * 4;
            float4 v0=p0[0], v1=p0[1], v2=p0[2], v3=p0[3];
            a0.x+=v0.x; a0.y+=v0.y; a0.z+=v0.z; a0.w+=v0.w;
            a1.x+=v1.x; a1.y+=v1.y; a1.z+=v1.z; a1.w+=v1.w;
            a2.x+=v2.x; a2.y+=v2.y; a2.z+=v2.z; a2.w+=v2.w;
            a3.x+=v3.x; a3.y+=v3.y; a3.z+=v3.z; a3.w+=v3.w;
        }
    } else {
        a0 = a1 = a2 = a3 = make_float4(0,0,0,0);
    }
    // store gathered tile
    *reinterpret_cast<float4*>(&hs[r][c0 +  0]) = a0;
    *reinterpret_cast<float4*>(&hs[r][c0 +  4]) = a1;
    *reinterpret_cast<float4*>(&hs[r][c0 +  8]) = a2;
    *reinterpret_cast<float4*>(&hs[r][c0 + 12]) = a3;
    __syncthreads();

    const float4* wv = reinterpret_cast<const float4*>(ws);
    int c4 = c0 >> 2;

    // ---- layer 1: t = relu(h @ W1 + b1)
    float t[16];
    #pragma unroll
    for (int jj = 0; jj < 16; jj++) t[jj] = bs1[c0 + jj];
    #pragma unroll 4
    for (int k = 0; k < 64; k++) {
        float hv = hs[r][k];
        float4 w0 = wv[k*16 + c4 + 0];
        float4 w1 = wv[k*16 + c4 + 1];
        float4 w2 = wv[k*16 + c4 + 2];
        float4 w3 = wv[k*16 + c4 + 3];
        t[0]  = fmaf(hv, w0.x, t[0]);  t[1]  = fmaf(hv, w0.y, t[1]);
        t[2]  = fmaf(hv, w0.z, t[2]);  t[3]  = fmaf(hv, w0.w, t[3]);
        t[4]  = fmaf(hv, w1.x, t[4]);  t[5]  = fmaf(hv, w1.y, t[5]);
        t[6]  = fmaf(hv, w1.z, t[6]);  t[7]  = fmaf(hv, w1.w, t[7]);
        t[8]  = fmaf(hv, w2.x, t[8]);  t[9]  = fmaf(hv, w2.y, t[9]);
        t[10] = fmaf(hv, w2.z, t[10]); t[11] = fmaf(hv, w2.w, t[11]);
        t[12] = fmaf(hv, w3.x, t[12]); t[13] = fmaf(hv, w3.y, t[13]);
        t[14] = fmaf(hv, w3.z, t[14]); t[15] = fmaf(hv, w3.w, t[15]);
    }
    #pragma unroll
    for (int jj = 0; jj < 16; jj++) t[jj] = fmaxf(t[jj], 0.f);

    __syncthreads();
    #pragma unroll
    for (int jj = 0; jj < 4; jj++)
        *reinterpret_cast<float4*>(&hs[r][c0 + jj*4]) =
            make_float4(t[jj*4+0], t[jj*4+1], t[jj*4+2], t[jj*4+3]);
    for (int i = tid; i < 4096; i += 256) ws[i] = W2[i];
    __syncthreads();

    // ---- layer 2: o = t @ W2 + b2
    float o[16];
    #pragma unroll
    for (int jj = 0; jj < 16; jj++) o[jj] = bs2[c0 + jj];
    #pragma unroll 4
    for (int k = 0; k < 64; k++) {
        float tv = hs[r][k];
        float4 w0 = wv[k*16 + c4 + 0];
        float4 w1 = wv[k*16 + c4 + 1];
        float4 w2 = wv[k*16 + c4 + 2];
        float4 w3 = wv[k*16 + c4 + 3];
        o[0]  = fmaf(tv, w0.x, o[0]);  o[1]  = fmaf(tv, w0.y, o[1]);
        o[2]  = fmaf(tv, w0.z, o[2]);  o[3]  = fmaf(tv, w0.w, o[3]);
        o[4]  = fmaf(tv, w1.x, o[4]);  o[5]  = fmaf(tv, w1.y, o[5]);
        o[6]  = fmaf(tv, w1.z, o[6]);  o[7]  = fmaf(tv, w1.w, o[7]);
        o[8]  = fmaf(tv, w2.x, o[8]);  o[9]  = fmaf(tv, w2.y, o[9]);
        o[10] = fmaf(tv, w2.z, o[10]); o[11] = fmaf(tv, w2.w, o[11]);
        o[12] = fmaf(tv, w3.x, o[12]); o[13] = fmaf(tv, w3.y, o[13]);
        o[14] = fmaf(tv, w3.z, o[14]); o[15] = fmaf(tv, w3.w, o[15]);
    }

    if (node < N_NODES) {
        float4* y4 = reinterpret_cast<float4*>(g_y + (size_t)node * D + c0);
        #pragma unroll
        for (int qq = 0; qq < 4; qq++)
            y4[qq] = make_float4(o[qq*4+0], o[qq*4+1], o[qq*4+2], o[qq*4+3]);
        #pragma unroll
        for (int jj = 0; jj < 16; jj++) {
            atomicAdd(&ssum[c0 + jj], o[jj]);
            atomicAdd(&ssq [c0 + jj], o[jj] * o[jj]);
        }
    }
    __syncthreads();
    if (tid < 64) {
        atomicAdd(&g_sum[tid], ssum[tid]);
        atomicAdd(&g_sq [tid], ssq [tid]);
    }
}

// ---------------- k4: epilogue (inline BN finalize) ----------------
__global__ __launch_bounds__(256) void k_epi(const float4* __restrict__ feat4,
                                             const float* __restrict__ gamma,
                                             const float* __restrict__ beta,
                                             float4* __restrict__ out4)
{
    __shared__ float4 s_scale[16], s_shift[16];
    int tid = threadIdx.x;
    if (tid < D) {
        float inv_n = 1.0f / (float)N_NODES;
        float mean = g_sum[tid] * inv_n;
        float var  = g_sq[tid] * inv_n - mean * mean;
        float sc   = gamma[tid] * rsqrtf(var + BN_EPS);
        float sh   = beta[tid] - mean * sc;
        reinterpret_cast<float*>(s_scale)[tid] = sc;
        reinterpret_cast<float*>(s_shift)[tid] = sh;
    }
    __syncthreads();

    const float4* y4 = reinterpret_cast<const float4*>(g_y);
    int total = N_NODES * D4;
    for (int i = blockIdx.x * blockDim.x + tid; i < total; i += gridDim.x * blockDim.x) {
        int c4 = i & 15;
        float4 y = y4[i];
        float4 s = s_scale[c4];
        float4 h = s_shift[c4];
        float4 f = feat4[i];
        float4 rr;
        rr.x = f.x + fmaxf(fmaf(y.x, s.x, h.x), 0.f);
        rr.y = f.y + fmaxf(fmaf(y.y, s.y, h.y), 0.f);
        rr.z = f.z + fmaxf(fmaf(y.z, s.z, h.z), 0.f);
        rr.w = f.w + fmaxf(fmaf(y.w, s.w, h.w), 0.f);
        out4[i] = rr;
    }
}

extern "C" void kernel_launch(void* const* d_in, const int* in_sizes, int n_in,
                              void* d_out, int out_size)
{
    const float4* feat4 = (const float4*)d_in[0];
    const int*    src   = (const int*)  d_in[1];
    const int*    dst   = (const int*)  d_in[2];
    const float*  eps   = (const float*)d_in[3];
    const float*  W1    = (const float*)d_in[4];
    const float*  b1    = (const float*)d_in[5];
    const float*  W2    = (const float*)d_in[6];
    const float*  b2    = (const float*)d_in[7];
    const float*  gamma = (const float*)d_in[8];
    const float*  beta  = (const float*)d_in[9];
    float4* out4 = (float4*)d_out;

    k_zero_deg <<<(N_NODES + 255) / 256, 256>>>();                    // idx 0
    k_bucket   <<<(N_EDGES + 255) / 256, 256>>>(src, dst);            // idx 1
    k_zero_sums<<<1, 128>>>();                                        // idx 2
    k_fused    <<<(N_NODES + 63) / 64, 256>>>(feat4, eps, W1, b1, W2, b2); // idx 3 (profiled)
    k_epi      <<<1184, 256>>>(feat4, gamma, beta, out4);             // idx 4
}

// round 4
// speedup vs baseline: 1.0303x; 1.0303x over previous
#include <cuda_runtime.h>
#include <cstdint>

#define N_NODES 100000
#define N_EDGES 1600000
#define D 64
#define D4 16
#define CAP 64
#define BN_EPS 1e-5f

// ---------------- scratch ----------------
__device__ float g_y [N_NODES * D];
__device__ int   g_deg[N_NODES];
__device__ int   g_srt[(size_t)N_NODES * CAP];
__device__ float g_sum[D];
__device__ float g_sq [D];

// ---------------- k0: zero degree + BN sums ----------------
__global__ void k_zero()
{
    int i = blockIdx.x * blockDim.x + threadIdx.x;
    if (i < N_NODES) g_deg[i] = 0;
    if (i < D) { g_sum[i] = 0.f; g_sq[i] = 0.f; }
}

// ---------------- k1: bucket edges by dst ----------------
__global__ void k_bucket(const int* __restrict__ src, const int* __restrict__ dst)
{
    int e = blockIdx.x * blockDim.x + threadIdx.x;
    if (e >= N_EDGES) return;
    int d = dst[e];
    int p = atomicAdd(&g_deg[d], 1);
    if (p < CAP) g_srt[(size_t)d * CAP + p] = src[e];
}

// ---------------- k2: fused gather + MLP + BN-stats ----------------
// 256 threads / 64 nodes per block.
// Gather phase: warp-per-node (8 nodes per warp, sequential), float2 per lane.
// MLP phase:   thread (r = tid/4, c0 = (tid%4)*16).
__global__ __launch_bounds__(256) void k_fused(const float2* __restrict__ feat2,
                                               const float* __restrict__ eps,
                                               const float* __restrict__ W1,
                                               const float* __restrict__ b1,
                                               const float* __restrict__ W2,
                                               const float* __restrict__ b2)
{
    __shared__ float hs[64][68];
    __shared__ float ws[4096];
    __shared__ float bs1[64], bs2[64];
    __shared__ float ssum[64], ssq[64];

    int tid  = threadIdx.x;
    int base = blockIdx.x * 64;
    int wid  = tid >> 5;
    int lane = tid & 31;

    // W1 + biases load (independent of gather)
    for (int i = tid; i < 4096; i += 256) ws[i] = W1[i];
    if (tid < 64) {
        bs1[tid] = b1[tid];
        bs2[tid] = b2[tid];
        ssum[tid] = 0.f;
        ssq [tid] = 0.f;
    }

    // ---- gather: warp w handles local rows w*8 .. w*8+7, one node at a time.
    float se = 1.0f + *eps;
    #pragma unroll 1
    for (int rr = 0; rr < 8; rr++) {
        int r    = wid * 8 + rr;
        int node = base + r;
        float2 acc = make_float2(0.f, 0.f);
        if (node < N_NODES) {
            float2 v = feat2[(size_t)node * 32 + lane];
            acc.x = se * v.x;
            acc.y = se * v.y;

            int dg = g_deg[node];
            if (dg > CAP) dg = CAP;
            const int* lst = g_srt + (size_t)node * CAP;

            int dg32  = (dg < 32) ? dg : 32;
            int myidx = (lane < dg32) ? lst[lane] : 0;   // lane-parallel index load

            int j = 0;
            for (; j + 4 <= dg32; j += 4) {
                int s0 = __shfl_sync(0xffffffffu, myidx, j + 0);
                int s1 = __shfl_sync(0xffffffffu, myidx, j + 1);
                int s2 = __shfl_sync(0xffffffffu, myidx, j + 2);
                int s3 = __shfl_sync(0xffffffffu, myidx, j + 3);
                float2 v0 = feat2[(size_t)s0 * 32 + lane];
                float2 v1 = feat2[(size_t)s1 * 32 + lane];
                float2 v2 = feat2[(size_t)s2 * 32 + lane];
                float2 v3 = feat2[(size_t)s3 * 32 + lane];
                acc.x += (v0.x + v1.x) + (v2.x + v3.x);
                acc.y += (v0.y + v1.y) + (v2.y + v3.y);
            }
            for (; j < dg32; j++) {
                int s = __shfl_sync(0xffffffffu, myidx, j);
                float2 v = feat2[(size_t)s * 32 + lane];
                acc.x += v.x; acc.y += v.y;
            }
            for (int jj = 32; jj < dg; jj++) {           // ultra-rare tail (deg > 32)
                int s = lst[jj];                         // uniform broadcast load
                float2 v = feat2[(size_t)s * 32 + lane];
                acc.x += v.x; acc.y += v.y;
            }
        }
        *reinterpret_cast<float2*>(&hs[r][lane * 2]) = acc;
    }
    __syncthreads();

    // ---- MLP mapping
    int r  = tid >> 2;
    int q  = tid & 3;
    int c0 = q * 16;
    int c4 = c0 >> 2;
    int node = base + r;
    const float4* wv = reinterpret_cast<const float4*>(ws);

    // layer 1: t = relu(h @ W1 + b1)
    float t[16];
    #pragma unroll
    for (int jj = 0; jj < 16; jj++) t[jj] = bs1[c0 + jj];
    #pragma unroll 4
    for (int k = 0; k < 64; k++) {
        float hv = hs[r][k];
        float4 w0 = wv[k*16 + c4 + 0];
        float4 w1 = wv[k*16 + c4 + 1];
        float4 w2 = wv[k*16 + c4 + 2];
        float4 w3 = wv[k*16 + c4 + 3];
        t[0]  = fmaf(hv, w0.x, t[0]);  t[1]  = fmaf(hv, w0.y, t[1]);
        t[2]  = fmaf(hv, w0.z, t[2]);  t[3]  = fmaf(hv, w0.w, t[3]);
        t[4]  = fmaf(hv, w1.x, t[4]);  t[5]  = fmaf(hv, w1.y, t[5]);
        t[6]  = fmaf(hv, w1.z, t[6]);  t[7]  = fmaf(hv, w1.w, t[7]);
        t[8]  = fmaf(hv, w2.x, t[8]);  t[9]  = fmaf(hv, w2.y, t[9]);
        t[10] = fmaf(hv, w2.z, t[10]); t[11] = fmaf(hv, w2.w, t[11]);
        t[12] = fmaf(hv, w3.x, t[12]); t[13] = fmaf(hv, w3.y, t[13]);
        t[14] = fmaf(hv, w3.z, t[14]); t[15] = fmaf(hv, w3.w, t[15]);
    }
    #pragma unroll
    for (int jj = 0; jj < 16; jj++) t[jj] = fmaxf(t[jj], 0.f);

    __syncthreads();
    #pragma unroll
    for (int jj = 0; jj < 4; jj++)
        *reinterpret_cast<float4*>(&hs[r][c0 + jj*4]) =
            make_float4(t[jj*4+0], t[jj*4+1], t[jj*4+2], t[jj*4+3]);
    for (int i = tid; i < 4096; i += 256) ws[i] = W2[i];
    __syncthreads();

    // layer 2: o = t @ W2 + b2
    float o[16];
    #pragma unroll
    for (int jj = 0; jj < 16; jj++) o[jj] = bs2[c0 + jj];
    #pragma unroll 4
    for (int k = 0; k < 64; k++) {
        float tv = hs[r][k];
        float4 w0 = wv[k*16 + c4 + 0];
        float4 w1 = wv[k*16 + c4 + 1];
        float4 w2 = wv[k*16 + c4 + 2];
        float4 w3 = wv[k*16 + c4 + 3];
        o[0]  = fmaf(tv, w0.x, o[0]);  o[1]  = fmaf(tv, w0.y, o[1]);
        o[2]  = fmaf(tv, w0.z, o[2]);  o[3]  = fmaf(tv, w0.w, o[3]);
        o[4]  = fmaf(tv, w1.x, o[4]);  o[5]  = fmaf(tv, w1.y, o[5]);
        o[6]  = fmaf(tv, w1.z, o[6]);  o[7]  = fmaf(tv, w1.w, o[7]);
        o[8]  = fmaf(tv, w2.x, o[8]);  o[9]  = fmaf(tv, w2.y, o[9]);
        o[10] = fmaf(tv, w2.z, o[10]); o[11] = fmaf(tv, w2.w, o[11]);
        o[12] = fmaf(tv, w3.x, o[12]); o[13] = fmaf(tv, w3.y, o[13]);
        o[14] = fmaf(tv, w3.z, o[14]); o[15] = fmaf(tv, w3.w, o[15]);
    }

    if (node < N_NODES) {
        float4* y4 = reinterpret_cast<float4*>(g_y + (size_t)node * D + c0);
        #pragma unroll
        for (int qq = 0; qq < 4; qq++)
            y4[qq] = make_float4(o[qq*4+0], o[qq*4+1], o[qq*4+2], o[qq*4+3]);
        #pragma unroll
        for (int jj = 0; jj < 16; jj++) {
            atomicAdd(&ssum[c0 + jj], o[jj]);
            atomicAdd(&ssq [c0 + jj], o[jj] * o[jj]);
        }
    }
    __syncthreads();
    if (tid < 64) {
        atomicAdd(&g_sum[tid], ssum[tid]);
        atomicAdd(&g_sq [tid], ssq [tid]);
    }
}

// ---------------- k3: epilogue (inline BN finalize) ----------------
__global__ __launch_bounds__(256) void k_epi(const float4* __restrict__ feat4,
                                             const float* __restrict__ gamma,
                                             const float* __restrict__ beta,
                                             float4* __restrict__ out4)
{
    __shared__ float4 s_scale[16], s_shift[16];
    int tid = threadIdx.x;
    if (tid < D) {
        float inv_n = 1.0f / (float)N_NODES;
        float mean = g_sum[tid] * inv_n;
        float var  = g_sq[tid] * inv_n - mean * mean;
        float sc   = gamma[tid] * rsqrtf(var + BN_EPS);
        float sh   = beta[tid] - mean * sc;
        reinterpret_cast<float*>(s_scale)[tid] = sc;
        reinterpret_cast<float*>(s_shift)[tid] = sh;
    }
    __syncthreads();

    const float4* y4 = reinterpret_cast<const float4*>(g_y);
    int total = N_NODES * D4;
    for (int i = blockIdx.x * blockDim.x + tid; i < total; i += gridDim.x * blockDim.x) {
        int c4 = i & 15;
        float4 y = y4[i];
        float4 s = s_scale[c4];
        float4 h = s_shift[c4];
        float4 f = feat4[i];
        float4 rr;
        rr.x = f.x + fmaxf(fmaf(y.x, s.x, h.x), 0.f);
        rr.y = f.y + fmaxf(fmaf(y.y, s.y, h.y), 0.f);
        rr.z = f.z + fmaxf(fmaf(y.z, s.z, h.z), 0.f);
        rr.w = f.w + fmaxf(fmaf(y.w, s.w, h.w), 0.f);
        out4[i] = rr;
    }
}

extern "C" void kernel_launch(void* const* d_in, const int* in_sizes, int n_in,
                              void* d_out, int out_size)
{
    const float*  feat  = (const float*)d_in[0];
    const int*    src   = (const int*)  d_in[1];
    const int*    dst   = (const int*)  d_in[2];
    const float*  eps   = (const float*)d_in[3];
    const float*  W1    = (const float*)d_in[4];
    const float*  b1    = (const float*)d_in[5];
    const float*  W2    = (const float*)d_in[6];
    const float*  b2    = (const float*)d_in[7];
    const float*  gamma = (const float*)d_in[8];
    const float*  beta  = (const float*)d_in[9];
    float4* out4 = (float4*)d_out;

    k_zero  <<<(N_NODES + 255) / 256, 256>>>();
    k_bucket<<<(N_EDGES + 255) / 256, 256>>>(src, dst);
    k_fused <<<(N_NODES + 63) / 64, 256>>>((const float2*)feat, eps, W1, b1, W2, b2);
    k_epi   <<<1184, 256>>>((const float4*)feat, gamma, beta, out4);
}

// round 5
// speedup vs baseline: 1.4268x; 1.3848x over previous
#include <cuda_runtime.h>
#include <cstdint>

#define N_NODES 100000
#define N_EDGES 1600000
#define D 64
#define D4 16
#define CAP 64
#define BN_EPS 1e-5f

typedef unsigned long long ull;

// packed f32x2 ops (Blackwell FFMA2 path — only via PTX)
#define FMA2(d,a,b,c) asm("fma.rn.f32x2 %0, %1, %2, %3;" : "=l"(d) : "l"(a), "l"(b), "l"(c))
#define ADD2(d,a,b)   asm("add.rn.f32x2 %0, %1, %2;"     : "=l"(d) : "l"(a), "l"(b))
#define MUL2(d,a,b)   asm("mul.rn.f32x2 %0, %1, %2;"     : "=l"(d) : "l"(a), "l"(b))
#define PK2(d,lo,hi)  asm("mov.b64 %0, {%1, %2};"        : "=l"(d) : "f"(lo), "f"(hi))
#define UPK2(lo,hi,s) asm("mov.b64 {%0, %1}, %2;"        : "=f"(lo), "=f"(hi) : "l"(s))

// ---------------- scratch ----------------
__device__ float g_y [N_NODES * D];
__device__ int   g_deg[N_NODES];
__device__ int   g_srt[(size_t)N_NODES * CAP];
__device__ float g_sum[D];
__device__ float g_sq [D];

// ---------------- k0: zero degree + BN sums ----------------
__global__ void k_zero()
{
    int i = blockIdx.x * blockDim.x + threadIdx.x;
    if (i < N_NODES) g_deg[i] = 0;
    if (i < D) { g_sum[i] = 0.f; g_sq[i] = 0.f; }
}

// ---------------- k1: bucket edges by dst ----------------
__global__ void k_bucket(const int* __restrict__ src, const int* __restrict__ dst)
{
    int e = blockIdx.x * blockDim.x + threadIdx.x;
    if (e >= N_EDGES) return;
    int d = dst[e];
    int p = atomicAdd(&g_deg[d], 1);
    if (p < CAP) g_srt[(size_t)d * CAP + p] = src[e];
}

// ---------------- k2: fused gather + MLP + BN-stats ----------------
__global__ __launch_bounds__(256) void k_fused(const ull* __restrict__ featp,
                                               const float* __restrict__ eps,
                                               const float* __restrict__ W1,
                                               const float* __restrict__ b1,
                                               const float* __restrict__ W2,
                                               const float* __restrict__ b2)
{
    __shared__ float hs[64][68];
    __shared__ float ws[8192];          // W1 | W2
    __shared__ float bs1[64], bs2[64];

    int tid  = threadIdx.x;
    int base = blockIdx.x * 64;
    int wid  = tid >> 5;
    int lane = tid & 31;
    const unsigned FULL = 0xffffffffu;

    // weights + biases load (overlaps gather latency)
    for (int i = tid; i < 4096; i += 256) ws[i]        = W1[i];
    for (int i = tid; i < 4096; i += 256) ws[4096 + i] = W2[i];
    if (tid < 64) { bs1[tid] = b1[tid]; bs2[tid] = b2[tid]; }

    // ---- gather: warp handles 8 nodes; pipelined deg/idx prefetch ----
    int wr0    = wid * 8;
    int gnode0 = base + wr0;

    int dgl = 0;
    if (lane < 8) {
        int n = gnode0 + lane;
        if (n < N_NODES) dgl = g_deg[n];
    }
    int dg_next = __shfl_sync(FULL, dgl, 0);
    if (dg_next > CAP) dg_next = CAP;
    int nxt = 0;
    {
        int lim = (dg_next < 32) ? dg_next : 32;
        if (gnode0 < N_NODES && lane < lim)
            nxt = g_srt[(size_t)gnode0 * CAP + lane];
    }

    ull se2;
    {
        float se = 1.0f + *eps;
        PK2(se2, se, se);
    }

    #pragma unroll 1
    for (int rr = 0; rr < 8; rr++) {
        int node  = gnode0 + rr;
        int dg    = dg_next;
        int myidx = nxt;
        if (rr < 7) {
            dg_next = __shfl_sync(FULL, dgl, rr + 1);
            if (dg_next > CAP) dg_next = CAP;
            int n1  = node + 1;
            int lim = (dg_next < 32) ? dg_next : 32;
            nxt = (n1 < N_NODES && lane < lim) ? g_srt[(size_t)n1 * CAP + lane] : 0;
        }

        ull acc = 0ull;
        if (node < N_NODES) {
            ull v = featp[(size_t)node * 32 + lane];
            MUL2(acc, se2, v);

            int dg32 = (dg < 32) ? dg : 32;
            int j = 0;
            for (; j + 4 <= dg32; j += 4) {
                int s0 = __shfl_sync(FULL, myidx, j + 0);
                int s1 = __shfl_sync(FULL, myidx, j + 1);
                int s2 = __shfl_sync(FULL, myidx, j + 2);
                int s3 = __shfl_sync(FULL, myidx, j + 3);
                ull v0 = featp[(size_t)s0 * 32 + lane];
                ull v1 = featp[(size_t)s1 * 32 + lane];
                ull v2 = featp[(size_t)s2 * 32 + lane];
                ull v3 = featp[(size_t)s3 * 32 + lane];
                ull t01, t23, t;
                ADD2(t01, v0, v1);
                ADD2(t23, v2, v3);
                ADD2(t, t01, t23);
                ADD2(acc, acc, t);
            }
            for (; j < dg32; j++) {
                int s = __shfl_sync(FULL, myidx, j);
                ull v = featp[(size_t)s * 32 + lane];
                ADD2(acc, acc, v);
            }
            for (int jj = 32; jj < dg; jj++) {          // rare tail
                int s = g_srt[(size_t)node * CAP + jj];
                ull v = featp[(size_t)s * 32 + lane];
                ADD2(acc, acc, v);
            }
        }
        *reinterpret_cast<ull*>(&hs[wr0 + rr][lane * 2]) = acc;
    }
    __syncthreads();

    // ---- MLP mapping: r = tid/4 (row), c0 = (tid%4)*16 (16 output cols)
    int r    = tid >> 2;
    int c0   = (tid & 3) * 16;
    int node = base + r;

    // layer 1: t = relu(h @ W1 + b1)   (f32x2 packed)
    ull t2[8];
    #pragma unroll
    for (int j = 0; j < 8; j++) PK2(t2[j], bs1[c0 + 2*j], bs1[c0 + 2*j + 1]);
    #pragma unroll 4
    for (int k = 0; k < 64; k++) {
        float hv = hs[r][k];
        ull hv2; PK2(hv2, hv, hv);
        const ulonglong2* wp = reinterpret_cast<const ulonglong2*>(ws + (k << 6) + c0);
        ulonglong2 wa = wp[0], wb = wp[1], wc = wp[2], wd = wp[3];
        FMA2(t2[0], hv2, wa.x, t2[0]); FMA2(t2[1], hv2, wa.y, t2[1]);
        FMA2(t2[2], hv2, wb.x, t2[2]); FMA2(t2[3], hv2, wb.y, t2[3]);
        FMA2(t2[4], hv2, wc.x, t2[4]); FMA2(t2[5], hv2, wc.y, t2[5]);
        FMA2(t2[6], hv2, wd.x, t2[6]); FMA2(t2[7], hv2, wd.y, t2[7]);
    }
    float tv[16];
    #pragma unroll
    for (int j = 0; j < 8; j++) {
        float lo, hi;
        UPK2(lo, hi, t2[j]);
        tv[2*j]   = fmaxf(lo, 0.f);
        tv[2*j+1] = fmaxf(hi, 0.f);
    }
    __syncthreads();
    #pragma unroll
    for (int j = 0; j < 4; j++)
        *reinterpret_cast<float4*>(&hs[r][c0 + j*4]) =
            make_float4(tv[j*4+0], tv[j*4+1], tv[j*4+2], tv[j*4+3]);
    __syncthreads();

    // layer 2: o = t @ W2 + b2
    ull o2[8];
    #pragma unroll
    for (int j = 0; j < 8; j++) PK2(o2[j], bs2[c0 + 2*j], bs2[c0 + 2*j + 1]);
    #pragma unroll 4
    for (int k = 0; k < 64; k++) {
        float hv = hs[r][k];
        ull hv2; PK2(hv2, hv, hv);
        const ulonglong2* wp = reinterpret_cast<const ulonglong2*>(ws + 4096 + (k << 6) + c0);
        ulonglong2 wa = wp[0], wb = wp[1], wc = wp[2], wd = wp[3];
        FMA2(o2[0], hv2, wa.x, o2[0]); FMA2(o2[1], hv2, wa.y, o2[1]);
        FMA2(o2[2], hv2, wb.x, o2[2]); FMA2(o2[3], hv2, wb.y, o2[3]);
        FMA2(o2[4], hv2, wc.x, o2[4]); FMA2(o2[5], hv2, wc.y, o2[5]);
        FMA2(o2[6], hv2, wd.x, o2[6]); FMA2(o2[7], hv2, wd.y, o2[7]);
    }
    float ov[16];
    #pragma unroll
    for (int j = 0; j < 8; j++) UPK2(ov[2*j], ov[2*j+1], o2[j]);

    if (node < N_NODES) {
        float4* y4 = reinterpret_cast<float4*>(g_y + (size_t)node * D + c0);
        #pragma unroll
        for (int j = 0; j < 4; j++)
            y4[j] = make_float4(ov[j*4+0], ov[j*4+1], ov[j*4+2], ov[j*4+3]);
    }

    // ---- BN stats: column reduce via hs (no smem atomics) ----
    __syncthreads();                     // all layer-2 reads of hs done
    if (node >= N_NODES) {
        #pragma unroll
        for (int j = 0; j < 16; j++) ov[j] = 0.f;
    }
    #pragma unroll
    for (int j = 0; j < 4; j++)
        *reinterpret_cast<float4*>(&hs[r][c0 + j*4]) =
            make_float4(ov[j*4+0], ov[j*4+1], ov[j*4+2], ov[j*4+3]);
    __syncthreads();
    if (tid < 64) {
        float s = 0.f, q = 0.f;
        #pragma unroll 8
        for (int row = 0; row < 64; row++) {
            float v = hs[row][tid];
            s += v;
            q = fmaf(v, v, q);
        }
        atomicAdd(&g_sum[tid], s);
        atomicAdd(&g_sq [tid], q);
    }
}

// ---------------- k3: epilogue (inline BN finalize) ----------------
__global__ __launch_bounds__(256) void k_epi(const float4* __restrict__ feat4,
                                             const float* __restrict__ gamma,
                                             const float* __restrict__ beta,
                                             float4* __restrict__ out4)
{
    __shared__ float4 s_scale[16], s_shift[16];
    int tid = threadIdx.x;
    if (tid < D) {
        float inv_n = 1.0f / (float)N_NODES;
        float mean = g_sum[tid] * inv_n;
        float var  = g_sq[tid] * inv_n - mean * mean;
        float sc   = gamma[tid] * rsqrtf(var + BN_EPS);
        float sh   = beta[tid] - mean * sc;
        reinterpret_cast<float*>(s_scale)[tid] = sc;
        reinterpret_cast<float*>(s_shift)[tid] = sh;
    }
    __syncthreads();

    const float4* y4 = reinterpret_cast<const float4*>(g_y);
    int total = N_NODES * D4;
    for (int i = blockIdx.x * blockDim.x + tid; i < total; i += gridDim.x * blockDim.x) {
        int c4 = i & 15;
        float4 y = y4[i];
        float4 s = s_scale[c4];
        float4 h = s_shift[c4];
        float4 f = feat4[i];
        float4 rr;
        rr.x = f.x + fmaxf(fmaf(y.x, s.x, h.x), 0.f);
        rr.y = f.y + fmaxf(fmaf(y.y, s.y, h.y), 0.f);
        rr.z = f.z + fmaxf(fmaf(y.z, s.z, h.z), 0.f);
        rr.w = f.w + fmaxf(fmaf(y.w, s.w, h.w), 0.f);
        out4[i] = rr;
    }
}

extern "C" void kernel_launch(void* const* d_in, const int* in_sizes, int n_in,
                              void* d_out, int out_size)
{
    const float*  feat  = (const float*)d_in[0];
    const int*    src   = (const int*)  d_in[1];
    const int*    dst   = (const int*)  d_in[2];
    const float*  eps   = (const float*)d_in[3];
    const float*  W1    = (const float*)d_in[4];
    const float*  b1    = (const float*)d_in[5];
    const float*  W2    = (const float*)d_in[6];
    const float*  b2    = (const float*)d_in[7];
    const float*  gamma = (const float*)d_in[8];
    const float*  beta  = (const float*)d_in[9];
    float4* out4 = (float4*)d_out;

    k_zero  <<<(N_NODES + 255) / 256, 256>>>();
    k_bucket<<<(N_EDGES + 255) / 256, 256>>>(src, dst);
    k_fused <<<(N_NODES + 63) / 64, 256>>>((const ull*)feat, eps, W1, b1, W2, b2);
    k_epi   <<<1184, 256>>>((const float4*)feat, gamma, beta, out4);
}